// round 16
// baseline (speedup 1.0000x reference)
#include <cuda_runtime.h>

// Problem constants
#define BN_  4
#define C_   256
#define NPX_ 4096    // 64*64
#define O_   64
#define G_   16
#define GC_  16
#define GS_  4       // groups per block
#define KK_  49      // 7*7
#define KPAD 56      // w2 k stride: 7 chunks x 8 floats (7 live + 1 pad)

typedef unsigned long long ull;

// --------- scratch (allocation-free: __device__ globals) ----------
__device__ __align__(16) float g_t[BN_ * O_ * NPX_];     // t, [b][o][px], 4 MB
__device__ __align__(16) float g_w1t[C_ * O_];           // [c][o], BN-folded
__device__ float g_b1[O_];
__device__ __align__(16) float g_w2t[G_ * O_ * KPAD];    // [g][o][kc*8+j]

// --------- f32x2 helpers (Blackwell packed fp32) ----------
__device__ __forceinline__ ull pk(float a, float b) {
    ull r; asm("mov.b64 %0,{%1,%2};" : "=l"(r) : "f"(a), "f"(b)); return r;
}
__device__ __forceinline__ ull dupf(float a) {
    ull r; asm("mov.b64 %0,{%1,%1};" : "=l"(r) : "f"(a)); return r;
}
__device__ __forceinline__ void fma2(ull& d, ull a, ull b) {
    asm("fma.rn.f32x2 %0,%1,%2,%0;" : "+l"(d) : "l"(a), "l"(b));
}
__device__ __forceinline__ void unpk(ull v, float& a, float& b) {
    asm("mov.b64 {%0,%1},%2;" : "=f"(a), "=f"(b) : "l"(v));
}

// =================================================================
// Prep: BN-fold + transpose w1 -> [c][o]; w2 -> [g][o][kc*8+j] chunks.
// =================================================================
__global__ __launch_bounds__(256) void prep_kernel(const float* __restrict__ w1,
                                                   const float* __restrict__ gamma,
                                                   const float* __restrict__ beta,
                                                   const float* __restrict__ mean,
                                                   const float* __restrict__ var,
                                                   const float* __restrict__ w2) {
    int tid = blockIdx.x * 256 + threadIdx.x;
    int nthr = gridDim.x * 256;

    for (int i = tid; i < C_ * O_; i += nthr) {
        int c = i >> 6, o = i & 63;
        float sc = gamma[o] * rsqrtf(var[o] + 1e-5f);
        g_w1t[i] = w1[(size_t)o * C_ + c] * sc;
    }
    if (tid < O_) {
        float sc = gamma[tid] * rsqrtf(var[tid] + 1e-5f);
        g_b1[tid] = beta[tid] - mean[tid] * sc;
    }
    // w2t[g][o][kc*8+j] = w2[g*49 + kc*7 + j][o]  (j<7; j==7 -> 0)
    for (int i = tid; i < G_ * O_ * KPAD; i += nthr) {
        int kk = i % KPAD;
        int go = i / KPAD;
        int g = go >> 6, o = go & 63;
        int kc = kk >> 3, j = kk & 7;
        float v = 0.f;
        if (j < 7) v = w2[((size_t)(g * KK_ + kc * 7 + j)) * O_ + o];
        g_w2t[i] = v;
    }
}

// =================================================================
// conv1: t[b][o][px] = relu(sum_c w1t[c][o]*x + b1[o])   (o-major out)
// Block: 128 threads, 32 px x 64 o, grid 512. Thread: 2px x 8o.
// =================================================================
#define WS1 68
__global__ __launch_bounds__(128) void conv1_kernel(const float* __restrict__ x) {
    __shared__ __align__(16) float xs[32 * 32];   // [c][px]
    __shared__ __align__(16) float ws[32 * WS1];  // [c][o] (+pad)

    int tid = threadIdx.x;
    int bpx0 = blockIdx.x * 32;
    int bb = bpx0 / NPX_;
    int pxbase = bpx0 % NPX_;
    const float* xb = x + (size_t)bb * C_ * NPX_ + pxbase;

    int to = tid & 7, tp = tid >> 3;
    int p0 = tp * 2, o0 = to * 8;

    ull acc0[4] = {0, 0, 0, 0};   // px p0,   o-pairs
    ull acc1[4] = {0, 0, 0, 0};   // px p0+1

    for (int cc = 0; cc < C_; cc += 32) {
        __syncthreads();
#pragma unroll
        for (int i = 0; i < 8; i++) {
            int idx = tid + i * 128;
            int c = idx >> 5, low = idx & 31;
            xs[c * 32 + low] = xb[(size_t)(cc + c) * NPX_ + low];
        }
#pragma unroll
        for (int i = 0; i < 16; i++) {
            int idx = tid + i * 128;
            int c = idx >> 6, o = idx & 63;
            ws[c * WS1 + o] = g_w1t[(cc + c) * O_ + o];
        }
        __syncthreads();
#pragma unroll
        for (int c = 0; c < 32; c++) {
            float2 xv = *(const float2*)&xs[c * 32 + p0];
            ull x0d = dupf(xv.x), x1d = dupf(xv.y);
            ulonglong2 wA = *(const ulonglong2*)&ws[c * WS1 + o0];
            ulonglong2 wB = *(const ulonglong2*)&ws[c * WS1 + o0 + 4];
            fma2(acc0[0], wA.x, x0d); fma2(acc0[1], wA.y, x0d);
            fma2(acc0[2], wB.x, x0d); fma2(acc0[3], wB.y, x0d);
            fma2(acc1[0], wA.x, x1d); fma2(acc1[1], wA.y, x1d);
            fma2(acc1[2], wB.x, x1d); fma2(acc1[3], wB.y, x1d);
        }
    }

    // epilogue: bias+relu, o-major stores (float2 over the 2 px)
    int pxg = pxbase + p0;
#pragma unroll
    for (int j = 0; j < 4; j++) {
        float a0, a1, b0, b1;
        unpk(acc0[j], a0, a1);   // px0: o0+2j, o0+2j+1
        unpk(acc1[j], b0, b1);   // px1
        int oA = o0 + 2 * j, oB = oA + 1;
        float biasA = g_b1[oA], biasB = g_b1[oB];
        float2 vA = make_float2(fmaxf(a0 + biasA, 0.f), fmaxf(b0 + biasA, 0.f));
        float2 vB = make_float2(fmaxf(a1 + biasB, 0.f), fmaxf(b1 + biasB, 0.f));
        *(float2*)&g_t[((size_t)(bb * O_ + oA)) * NPX_ + pxg] = vA;
        *(float2*)&g_t[((size_t)(bb * O_ + oB)) * NPX_ + pxg] = vB;
    }
}

// =================================================================
// Fused conv2 + involution, 4 groups/block (grid = 1024).
// conv2 axis flipped to px-pairs: t_s is px-major [o][64px]; one
// LDS.128 yields 2 f32x2 t-pairs; w is the dup'd broadcast scalar.
// 112 threads = 16 px-quads x 7 k-chunks (49 = 7x7, no dead k).
// =================================================================
#define XG_CH 228              // xg channel stride: footprint 222, ==4 mod 32
#define SM_T   0                           // t_s [64o][64px] 16KB
#define SM_XG  (64 * 64)
#define SM_W2  (SM_XG + 16 * XG_CH)
#define SM_WT  (SM_W2 + 64 * KPAD)
#define SM_TOT (SM_WT + KK_ * 64)
#define SMEM_BYTES (SM_TOT * 4)

__global__ __launch_bounds__(256) void inv_kernel(const float* __restrict__ x,
                                                  const float* __restrict__ b2,
                                                  float* __restrict__ out) {
    extern __shared__ __align__(16) float sm[];
    float* t_s  = sm + SM_T;    // [64o][64px]
    float* xg   = sm + SM_XG;   // [16c][228]
    float* w2s  = sm + SM_W2;   // [64o][56]
    float* wt_s = sm + SM_WT;   // [49k][64px]

    int tid = threadIdx.x;
    int bid = blockIdx.x;
    int gs = bid & (GS_ - 1);
    int tile = (bid >> 2) & 63;
    int b = bid >> 8;
    int y0 = (tile >> 3) * 8, x0 = (tile & 7) * 8;
    const float* xb = x + (size_t)b * C_ * NPX_;

    bool interior = (y0 >= 8) && (y0 <= 48) && (x0 >= 8) && (x0 <= 48);

    // stage t tile px-major: t_s[o][pxl] from g_t[b][o][spatial]
#pragma unroll
    for (int i = 0; i < 16; i++) {
        int idx = tid + i * 256;
        int o = idx >> 6, pxl = idx & 63;
        int r = pxl >> 3, cx = pxl & 7;
        t_s[o * 64 + pxl] =
            g_t[((size_t)(b * O_ + o)) * NPX_ + (y0 + r) * 64 + (x0 + cx)];
    }

    // conv2 coords: 112 live threads = quad(16) x kc(7)
    int quad = tid & 15, kc = tid >> 4;
    // involution coords: ci in LOW bits (wt loads broadcast per warp)
    int ci = tid & 15, pxq = tid >> 4;
    int px0 = pxq * 4;
    int yloc = pxq >> 1, x0loc = (pxq & 1) * 4;

#pragma unroll 1
    for (int gi = 0; gi < GS_; gi++) {
        int g = gs * GS_ + gi;
        __syncthreads();  // prev involution done with xg/wt_s; t_s staged (gi==0)

        // stage x group halo (14x14 per channel)
        if (interior) {
            for (int idx = tid; idx < 16 * 196; idx += 256) {
                int c = idx / 196, rem = idx - c * 196;
                int rr = rem / 14, xx = rem - rr * 14;
                xg[c * XG_CH + rr * 16 + xx] =
                    xb[(size_t)(g * GC_ + c) * NPX_ + (y0 + rr - 3) * 64 + (x0 + xx - 3)];
            }
        } else {
            for (int idx = tid; idx < 16 * 196; idx += 256) {
                int c = idx / 196, rem = idx - c * 196;
                int rr = rem / 14, xx = rem - rr * 14;
                int gy = y0 + rr - 3, gx = x0 + xx - 3;
                float v = 0.f;
                if (gy >= 0 && gy < 64 && gx >= 0 && gx < 64)
                    v = xb[(size_t)(g * GC_ + c) * NPX_ + gy * 64 + gx];
                xg[c * XG_CH + rr * 16 + xx] = v;
            }
        }
        // stage w2 slice (pre-chunked, stride-1 copy; 3584 = 14*256)
        {
            const float* src = g_w2t + (size_t)g * O_ * KPAD;
#pragma unroll
            for (int i = 0; i < 14; i++)
                w2s[tid + i * 256] = src[tid + i * 256];
        }
        __syncthreads();

        // ---- conv2: 4 px (2 f32x2 pairs) x 7 k per thread ----
        if (tid < 112) {
            int kbase = kc * 7;
            ull a01[7], a23[7];
#pragma unroll
            for (int j = 0; j < 7; j++) {
                ull bv = dupf(b2[g * KK_ + kbase + j]);
                a01[j] = bv; a23[j] = bv;
            }
            const float* w2p = w2s + kc * 8;
            const float* tp = t_s + quad * 4;
#pragma unroll 4
            for (int o = 0; o < 64; o++) {
                ulonglong2 tq = *(const ulonglong2*)(tp + o * 64);
                float4 w0 = *(const float4*)(w2p + o * KPAD);
                float4 w1 = *(const float4*)(w2p + o * KPAD + 4);
                ull d;
                d = dupf(w0.x); fma2(a01[0], tq.x, d); fma2(a23[0], tq.y, d);
                d = dupf(w0.y); fma2(a01[1], tq.x, d); fma2(a23[1], tq.y, d);
                d = dupf(w0.z); fma2(a01[2], tq.x, d); fma2(a23[2], tq.y, d);
                d = dupf(w0.w); fma2(a01[3], tq.x, d); fma2(a23[3], tq.y, d);
                d = dupf(w1.x); fma2(a01[4], tq.x, d); fma2(a23[4], tq.y, d);
                d = dupf(w1.y); fma2(a01[5], tq.x, d); fma2(a23[5], tq.y, d);
                d = dupf(w1.z); fma2(a01[6], tq.x, d); fma2(a23[6], tq.y, d);
            }
#pragma unroll
            for (int j = 0; j < 7; j++) {
                ulonglong2 v;
                v.x = a01[j]; v.y = a23[j];
                *(ulonglong2*)&wt_s[(kbase + j) * 64 + quad * 4] = v;
            }
        }
        __syncthreads();

        // ---- involution: 4 adjacent-x pixels x 1 channel per thread ----
        {
            ull acc01 = 0ull, acc23 = 0ull;
            const float* xgc = xg + ci * XG_CH + yloc * 16 + x0loc;
            const float* wtp = wt_s + px0;
#pragma unroll
            for (int ky = 0; ky < 7; ky++) {
                const float* rowp = xgc + ky * 16;
                float4 rA = *(const float4*)rowp;
                float4 rB = *(const float4*)(rowp + 4);
                float2 rC = *(const float2*)(rowp + 8);
                float xr[10] = {rA.x, rA.y, rA.z, rA.w,
                                rB.x, rB.y, rB.z, rB.w,
                                rC.x, rC.y};
                ull xp[9];
#pragma unroll
                for (int j = 0; j < 9; j++) xp[j] = pk(xr[j], xr[j + 1]);
#pragma unroll
                for (int kx = 0; kx < 7; kx++) {
                    ulonglong2 wq = *(const ulonglong2*)(wtp + (ky * 7 + kx) * 64);
                    fma2(acc01, wq.x, xp[kx]);
                    fma2(acc23, wq.y, xp[kx + 2]);
                }
            }
            float v0, v1, v2, v3;
            unpk(acc01, v0, v1);
            unpk(acc23, v2, v3);
            int gy = y0 + yloc, gx = x0 + x0loc;
            *(float4*)&out[((size_t)b * C_ + g * GC_ + ci) * NPX_ + gy * 64 + gx] =
                make_float4(v0, v1, v2, v3);
        }
    }
}

// =================================================================
extern "C" void kernel_launch(void* const* d_in, const int* in_sizes, int n_in,
                              void* d_out, int out_size) {
    const float* x     = (const float*)d_in[0];
    const float* w1    = (const float*)d_in[1];
    const float* gamma = (const float*)d_in[2];
    const float* beta  = (const float*)d_in[3];
    const float* mean  = (const float*)d_in[4];
    const float* var   = (const float*)d_in[5];
    const float* w2    = (const float*)d_in[6];
    const float* b2    = (const float*)d_in[7];
    float* out = (float*)d_out;

    cudaFuncSetAttribute(inv_kernel, cudaFuncAttributeMaxDynamicSharedMemorySize,
                         SMEM_BYTES);

    prep_kernel<<<224, 256>>>(w1, gamma, beta, mean, var, w2);
    conv1_kernel<<<BN_ * NPX_ / 32, 128>>>(x);
    inv_kernel<<<BN_ * 64 * GS_, 256, SMEM_BYTES>>>(x, b2, out);
}